// round 15
// baseline (speedup 1.0000x reference)
#include <cuda_runtime.h>
#include <math.h>

#define NN 100000
#define NE 3200000
#define HID 32
#define NG 1000
#define NPG 100
#define KTOP 35
#define SLOT 80   // max supported in-degree (Poisson(32); +8.5 sigma)
#define EB ((NE + 255) / 256)   // 12500 fill blocks
#define NB (NN / 32)            // 3125 gemm/agg blocks

// ---------------- scratch (static device globals; no allocation) ------------
__device__ int   g_cnt[NN];                       // in-degree (excl self)
__device__ int   g_slots[NN * SLOT];              // padded adjacency (src ids)
__device__ __align__(16) float g_hsA[NN * HID];   // ping
__device__ __align__(16) float g_hsB[NN * HID];   // pong
__device__ __align__(16) float g_feat[NN * 128];
__device__ __align__(16) float g_z[NG * 416];     // head conv output

// ===== merged: adjacency build (blocks [0,EB)) + layer-0 GEMM (rest) =========
// fill is atomic/latency-bound, gemm is issue-bound -> co-resident blocks
// overlap; gemm writes UNSCALED h (scaling needs g_cnt, done after).
__global__ void build_kernel(const int* __restrict__ ei,
                             const float* __restrict__ x,
                             const float* __restrict__ w) {
    if (blockIdx.x < EB) {
        int e = blockIdx.x * 256 + threadIdx.x;
        if (e < NE) {
            int d = ei[NE + e];
            int pos = atomicAdd(&g_cnt[d], 1);
            if (pos < SLOT) g_slots[d * SLOT + pos] = ei[e];
        }
        return;
    }
    __shared__ float s_wT[32 * 132];
    int tid = threadIdx.x;
    for (int i = tid; i < 128 * 32; i += 256) {
        int k = i >> 5, c = i & 31;
        s_wT[c * 132 + k] = w[i];
    }
    __syncthreads();
    int wi = tid >> 5, c = tid & 31;
    int n = (blockIdx.x - EB) * 32 + wi * 4;
    float acc0 = 0.f, acc1 = 0.f, acc2 = 0.f, acc3 = 0.f;
    const float4* wv4 = (const float4*)&s_wT[c * 132];
    const float4* r0 = (const float4*)&x[(n + 0) * 128];
    const float4* r1 = (const float4*)&x[(n + 1) * 128];
    const float4* r2 = (const float4*)&x[(n + 2) * 128];
    const float4* r3 = (const float4*)&x[(n + 3) * 128];
#pragma unroll 8
    for (int k4 = 0; k4 < 32; ++k4) {
        float4 wv = wv4[k4];
        float4 a = __ldg(r0 + k4);
        acc0 += wv.x * a.x + wv.y * a.y + wv.z * a.z + wv.w * a.w;
        a = __ldg(r1 + k4);
        acc1 += wv.x * a.x + wv.y * a.y + wv.z * a.z + wv.w * a.w;
        a = __ldg(r2 + k4);
        acc2 += wv.x * a.x + wv.y * a.y + wv.z * a.z + wv.w * a.w;
        a = __ldg(r3 + k4);
        acc3 += wv.x * a.x + wv.y * a.y + wv.z * a.z + wv.w * a.w;
    }
    g_hsA[(n + 0) * 32 + c] = acc0;   // unscaled h
    g_hsA[(n + 1) * 32 + c] = acc1;
    g_hsA[(n + 2) * 32 + c] = acc2;
    g_hsA[(n + 3) * 32 + c] = acc3;
}

// ---- scale hsA by rsqrt(deg) once degrees are final (float4 streaming) ------
__global__ void scale_kernel() {
    int i = blockIdx.x * 256 + threadIdx.x;      // over NN*8 float4s
    if (i < NN * 8) {
        float dn = rsqrtf((float)g_cnt[i >> 3] + 1.0f);
        float4 v = ((const float4*)g_hsA)[i];
        v.x *= dn; v.y *= dn; v.z *= dn; v.w *= dn;
        ((float4*)g_hsA)[i] = v;
    }
}

// ===== fused: agg(layer) + tanh + feat write + next-layer GEMM (IF=32) =======
// block = 256 threads = 32 nodes; warp = 4 nodes, 8 lanes/node (float4 chans).
__global__ void fused_kernel(const float* __restrict__ b,
                             const float* __restrict__ w,
                             int layer, int par) {
    __shared__ float s_wT[32 * 36];
    __shared__ float s_in[8][128];     // per-warp: 4 nodes x 32 channels
    const float4* hs4 = (const float4*)(par ? g_hsB : g_hsA);
    float*        hso = par ? g_hsA : g_hsB;
    int tid = threadIdx.x;
    for (int i = tid; i < 32 * 32; i += 256) {   // stage W transpose
        int k = i >> 5, c = i & 31;
        s_wT[c * 36 + k] = w[i];
    }
    __syncthreads();

    int warp = tid >> 5, lane = tid & 31;
    int group = lane >> 3, sub = lane & 7;
    int n = blockIdx.x * 32 + warp * 4 + group;

    float4 acc = hs4[n * 8 + sub];               // self-loop term
    int deg = g_cnt[n];
    int base = n * SLOT;
    int maxdeg = __reduce_max_sync(0xffffffffu, deg);
    for (int j = 0; j < maxdeg; j += 8) {
        int idx = (j + sub < deg) ? g_slots[base + j + sub] : 0;
#pragma unroll
        for (int k = 0; k < 8; ++k) {
            int s = __shfl_sync(0xffffffffu, idx, (group << 3) + k);
            if (j + k < deg) {
                float4 v = hs4[s * 8 + sub];
                acc.x += v.x; acc.y += v.y; acc.z += v.z; acc.w += v.w;
            }
        }
    }
    float dn = rsqrtf((float)deg + 1.0f);
    float4 bb = ((const float4*)b)[sub];
    float4 o;
    o.x = tanhf(dn * acc.x + bb.x);
    o.y = tanhf(dn * acc.y + bb.y);
    o.z = tanhf(dn * acc.z + bb.z);
    o.w = tanhf(dn * acc.w + bb.w);
    ((float4*)g_feat)[n * 32 + layer * 8 + sub] = o;
    ((float4*)&s_in[warp][0])[group * 8 + sub] = o;
    __syncwarp();

    // warp-local GEMM: hs_next = (tanh_out @ Wnext) * rsqrt(deg)
    int c = lane;
    float a0 = 0.f, a1 = 0.f, a2 = 0.f, a3 = 0.f;
    const float4* wv4 = (const float4*)&s_wT[c * 36];
    const float4* x0 = (const float4*)&s_in[warp][0];
    const float4* x1 = (const float4*)&s_in[warp][32];
    const float4* x2 = (const float4*)&s_in[warp][64];
    const float4* x3 = (const float4*)&s_in[warp][96];
#pragma unroll
    for (int k4 = 0; k4 < 8; ++k4) {
        float4 wv = wv4[k4];
        float4 a = x0[k4];
        a0 += wv.x * a.x + wv.y * a.y + wv.z * a.z + wv.w * a.w;
        a = x1[k4];
        a1 += wv.x * a.x + wv.y * a.y + wv.z * a.z + wv.w * a.w;
        a = x2[k4];
        a2 += wv.x * a.x + wv.y * a.y + wv.z * a.z + wv.w * a.w;
        a = x3[k4];
        a3 += wv.x * a.x + wv.y * a.y + wv.z * a.z + wv.w * a.w;
    }
    int nn = blockIdx.x * 32 + warp * 4;
    float e0 = rsqrtf((float)g_cnt[nn + 0] + 1.0f);
    float e1 = rsqrtf((float)g_cnt[nn + 1] + 1.0f);
    float e2 = rsqrtf((float)g_cnt[nn + 2] + 1.0f);
    float e3 = rsqrtf((float)g_cnt[nn + 3] + 1.0f);
    hso[(nn + 0) * 32 + c] = a0 * e0;
    hso[(nn + 1) * 32 + c] = a1 * e1;
    hso[(nn + 2) * 32 + c] = a2 * e2;
    hso[(nn + 3) * 32 + c] = a3 * e3;
}

// ---------------- final layer aggregation (layer 3): feat only ---------------
__global__ void agg_final_kernel(const float* __restrict__ b, int par) {
    const float4* hs4 = (const float4*)(par ? g_hsB : g_hsA);
    int t = blockIdx.x * 256 + threadIdx.x;
    int warp = t >> 5;
    int lane = threadIdx.x & 31;
    int group = lane >> 3, sub = lane & 7;
    int n = warp * 4 + group;
    if (n >= NN) return;
    float4 acc = hs4[n * 8 + sub];
    int deg = g_cnt[n];
    int base = n * SLOT;
    int maxdeg = __reduce_max_sync(0xffffffffu, deg);
    for (int j = 0; j < maxdeg; j += 8) {
        int idx = (j + sub < deg) ? g_slots[base + j + sub] : 0;
#pragma unroll
        for (int k = 0; k < 8; ++k) {
            int s = __shfl_sync(0xffffffffu, idx, (group << 3) + k);
            if (j + k < deg) {
                float4 v = hs4[s * 8 + sub];
                acc.x += v.x; acc.y += v.y; acc.z += v.z; acc.w += v.w;
            }
        }
    }
    float dn = rsqrtf((float)deg + 1.0f);
    float4 bb = ((const float4*)b)[sub];
    float4 o;
    o.x = tanhf(dn * acc.x + bb.x);
    o.y = tanhf(dn * acc.y + bb.y);
    o.z = tanhf(dn * acc.z + bb.z);
    o.w = tanhf(dn * acc.w + bb.w);
    ((float4*)g_feat)[n * 32 + 3 * 8 + sub] = o;
}

// ========== head part 1 (per graph): sort-pool + conv1 + pool + conv2 =======
__global__ void head1_kernel(const float* __restrict__ c1w, const float* __restrict__ c1b,
                             const float* __restrict__ c2w, const float* __restrict__ c2b) {
    __shared__ float s_last[NPG];
    __shared__ int   s_ord[KTOP];
    __shared__ float s_topT[128 * 36];  // transposed: [c][k], stride 36
    __shared__ float s_y[16 * KTOP];
    __shared__ float s_p[16 * 17];

    int g = blockIdx.x;
    int tid = threadIdx.x;
    int base = g * NPG;

    if (tid < NPG) s_last[tid] = g_feat[(base + tid) * 128 + 127];
    __syncthreads();

    // stable rank (descending; ties -> lower index first) == argsort(-x)
    if (tid < NPG) {
        float v = s_last[tid];
        int rank = 0;
#pragma unroll 4
        for (int j = 0; j < NPG; ++j) {
            float vj = s_last[j];
            rank += (vj > v) || (vj == v && j < tid);
        }
        if (rank < KTOP) s_ord[rank] = tid;
    }
    __syncthreads();

    for (int t = tid; t < KTOP * 128; t += 128) {
        int k = t >> 7, c = t & 127;
        s_topT[c * 36 + k] = g_feat[(base + s_ord[k]) * 128 + c];
    }
    __syncthreads();

    // conv1 (1x1) + relu : warp spans k -> conflict-free LDS
    for (int t = tid; t < 16 * KTOP; t += 128) {
        int o = t / KTOP, k = t - o * KTOP;
        float acc = c1b[o];
        const float* wr = &c1w[o * 128];
#pragma unroll 8
        for (int c = 0; c < 128; ++c) acc += wr[c] * s_topT[c * 36 + k];
        s_y[o * KTOP + k] = fmaxf(acc, 0.0f);
    }
    __syncthreads();

    for (int t = tid; t < 16 * 17; t += 128) {
        int o = t / 17, l = t - o * 17;
        s_p[t] = fmaxf(s_y[o * KTOP + 2 * l], s_y[o * KTOP + 2 * l + 1]);
    }
    __syncthreads();

    for (int t = tid; t < 32 * 13; t += 128) {
        int oc = t / 13, tt = t - oc * 13;
        float acc = c2b[oc];
        const float* wr = &c2w[oc * 80];
#pragma unroll
        for (int ic = 0; ic < 16; ++ic) {
            const float* pr = &s_p[ic * 17 + tt];
#pragma unroll
            for (int j = 0; j < 5; ++j) acc += wr[ic * 5 + j] * pr[j];
        }
        g_z[g * 416 + t] = fmaxf(acc, 0.0f);
    }
}

// ========== head part 2: g_cnt reset + fc1 (batched GEMM) + fc2 =============
// g_cnt is dead after agg_final (strictly before this kernel); resetting it
// here (125 blocks x 800 ints) rides in the s_z staging phase for free.
__global__ void head2_kernel(const float* __restrict__ f1w, const float* __restrict__ f1b,
                             const float* __restrict__ f2w, const float* __restrict__ f2b,
                             float* __restrict__ out) {
    __shared__ float s_z[8 * 416];
    __shared__ float s_f[8 * 128];
    int tid = threadIdx.x;
    int g0 = blockIdx.x * 8;

    // fused cleanup: each block clears its 800-int slice of g_cnt
    {
        int cbase = blockIdx.x * 800;
        for (int i = tid; i < 800; i += 256) g_cnt[cbase + i] = 0;
    }

    for (int i = tid; i < 8 * 416; i += 256)
        s_z[i] = g_z[g0 * 416 + i];
    __syncthreads();

    int warp = tid >> 5, lane = tid & 31;
    const float4* w4 = (const float4*)f1w;
    const float4* z4 = (const float4*)s_z;

    for (int o = warp; o < 128; o += 8) {
        float p0 = 0.f, p1 = 0.f, p2 = 0.f, p3 = 0.f;
        float p4 = 0.f, p5 = 0.f, p6 = 0.f, p7 = 0.f;
        for (int seg = lane; seg < 104; seg += 32) {
            float4 wv = __ldg(w4 + o * 104 + seg);
            float4 a;
            a = z4[0 * 104 + seg]; p0 += wv.x * a.x + wv.y * a.y + wv.z * a.z + wv.w * a.w;
            a = z4[1 * 104 + seg]; p1 += wv.x * a.x + wv.y * a.y + wv.z * a.z + wv.w * a.w;
            a = z4[2 * 104 + seg]; p2 += wv.x * a.x + wv.y * a.y + wv.z * a.z + wv.w * a.w;
            a = z4[3 * 104 + seg]; p3 += wv.x * a.x + wv.y * a.y + wv.z * a.z + wv.w * a.w;
            a = z4[4 * 104 + seg]; p4 += wv.x * a.x + wv.y * a.y + wv.z * a.z + wv.w * a.w;
            a = z4[5 * 104 + seg]; p5 += wv.x * a.x + wv.y * a.y + wv.z * a.z + wv.w * a.w;
            a = z4[6 * 104 + seg]; p6 += wv.x * a.x + wv.y * a.y + wv.z * a.z + wv.w * a.w;
            a = z4[7 * 104 + seg]; p7 += wv.x * a.x + wv.y * a.y + wv.z * a.z + wv.w * a.w;
        }
#pragma unroll
        for (int m = 16; m > 0; m >>= 1) {
            p0 += __shfl_xor_sync(0xffffffffu, p0, m);
            p1 += __shfl_xor_sync(0xffffffffu, p1, m);
            p2 += __shfl_xor_sync(0xffffffffu, p2, m);
            p3 += __shfl_xor_sync(0xffffffffu, p3, m);
            p4 += __shfl_xor_sync(0xffffffffu, p4, m);
            p5 += __shfl_xor_sync(0xffffffffu, p5, m);
            p6 += __shfl_xor_sync(0xffffffffu, p6, m);
            p7 += __shfl_xor_sync(0xffffffffu, p7, m);
        }
        if (lane == 0) {
            float bb = f1b[o];
            s_f[0 * 128 + o] = fmaxf(p0 + bb, 0.0f);
            s_f[1 * 128 + o] = fmaxf(p1 + bb, 0.0f);
            s_f[2 * 128 + o] = fmaxf(p2 + bb, 0.0f);
            s_f[3 * 128 + o] = fmaxf(p3 + bb, 0.0f);
            s_f[4 * 128 + o] = fmaxf(p4 + bb, 0.0f);
            s_f[5 * 128 + o] = fmaxf(p5 + bb, 0.0f);
            s_f[6 * 128 + o] = fmaxf(p6 + bb, 0.0f);
            s_f[7 * 128 + o] = fmaxf(p7 + bb, 0.0f);
        }
    }
    __syncthreads();

    float acc = f2w[lane]      * s_f[warp * 128 + lane]
              + f2w[lane + 32] * s_f[warp * 128 + lane + 32]
              + f2w[lane + 64] * s_f[warp * 128 + lane + 64]
              + f2w[lane + 96] * s_f[warp * 128 + lane + 96];
#pragma unroll
    for (int m = 16; m > 0; m >>= 1)
        acc += __shfl_xor_sync(0xffffffffu, acc, m);
    if (lane == 0) {
        float z = acc + f2b[0];
        out[g0 + warp] = 1.0f / (1.0f + expf(-z));
    }
}

// ---------------- launch -----------------------------------------------------
extern "C" void kernel_launch(void* const* d_in, const int* in_sizes, int n_in,
                              void* d_out, int out_size) {
    const float* x  = (const float*)d_in[0];
    const int*   ei = (const int*)d_in[1];   // int32 (JAX x64 disabled)
    const float* w[4] = {(const float*)d_in[3], (const float*)d_in[5],
                         (const float*)d_in[7], (const float*)d_in[9]};
    const float* b[4] = {(const float*)d_in[4], (const float*)d_in[6],
                         (const float*)d_in[8], (const float*)d_in[10]};
    const float* c1w = (const float*)d_in[11];
    const float* c1b = (const float*)d_in[12];
    const float* c2w = (const float*)d_in[13];
    const float* c2b = (const float*)d_in[14];
    const float* f1w = (const float*)d_in[15];
    const float* f1b = (const float*)d_in[16];
    const float* f2w = (const float*)d_in[17];
    const float* f2b = (const float*)d_in[18];
    float* out = (float*)d_out;

    // fill + layer-0 GEMM overlapped in one grid; scale once degrees final
    build_kernel<<<EB + NB, 256>>>(ei, x, w[0]);        // adjacency + h -> hsA
    scale_kernel<<<(NN * 8 + 255) / 256, 256>>>();      // hsA *= rsqrt(deg)

    fused_kernel<<<NB, 256>>>(b[0], w[1], 0, 0);        // read A -> write B
    fused_kernel<<<NB, 256>>>(b[1], w[2], 1, 1);        // read B -> write A
    fused_kernel<<<NB, 256>>>(b[2], w[3], 2, 0);        // read A -> write B
    agg_final_kernel<<<NB, 256>>>(b[3], 1);             // read B, feat only

    head1_kernel<<<NG, 128>>>(c1w, c1b, c2w, c2b);
    head2_kernel<<<NG / 8, 256>>>(f1w, f1b, f2w, f2b, out);  // + g_cnt reset
}

// round 16
// speedup vs baseline: 1.0037x; 1.0037x over previous
#include <cuda_runtime.h>
#include <math.h>

#define NN 100000
#define NE 3200000
#define HID 32
#define NG 1000
#define NPG 100
#define KTOP 35
#define SLOT 80   // max supported in-degree (Poisson(32); +8.5 sigma)
#define EB ((NE + 255) / 256)   // 12500 fill blocks
#define NB (NN / 32)            // 3125 gemm/agg blocks

// ---------------- scratch (static device globals; no allocation) ------------
__device__ int   g_cnt[NN];                       // in-degree (excl self)
__device__ int   g_slots[NN * SLOT];              // padded adjacency (src ids)
__device__ __align__(16) float g_hsA[NN * HID];   // ping
__device__ __align__(16) float g_hsB[NN * HID];   // pong
__device__ __align__(16) float g_feat[NN * 128];
__device__ __align__(16) float g_z[NG * 416];     // head conv output

// ===== merged: adjacency build (blocks [0,EB)) + layer-0 GEMM (rest) =========
// fill is atomic/latency-bound, gemm is issue-bound -> co-resident blocks
// overlap; gemm writes UNSCALED h (scaling needs g_cnt, done after).
__global__ void build_kernel(const int* __restrict__ ei,
                             const float* __restrict__ x,
                             const float* __restrict__ w) {
    if (blockIdx.x < EB) {
        int e = blockIdx.x * 256 + threadIdx.x;
        if (e < NE) {
            int d = ei[NE + e];
            int pos = atomicAdd(&g_cnt[d], 1);
            if (pos < SLOT) g_slots[d * SLOT + pos] = ei[e];
        }
        return;
    }
    __shared__ float s_wT[32 * 132];
    int tid = threadIdx.x;
    for (int i = tid; i < 128 * 32; i += 256) {
        int k = i >> 5, c = i & 31;
        s_wT[c * 132 + k] = w[i];
    }
    __syncthreads();
    int wi = tid >> 5, c = tid & 31;
    int n = (blockIdx.x - EB) * 32 + wi * 4;
    float acc0 = 0.f, acc1 = 0.f, acc2 = 0.f, acc3 = 0.f;
    const float4* wv4 = (const float4*)&s_wT[c * 132];
    const float4* r0 = (const float4*)&x[(n + 0) * 128];
    const float4* r1 = (const float4*)&x[(n + 1) * 128];
    const float4* r2 = (const float4*)&x[(n + 2) * 128];
    const float4* r3 = (const float4*)&x[(n + 3) * 128];
#pragma unroll 8
    for (int k4 = 0; k4 < 32; ++k4) {
        float4 wv = wv4[k4];
        float4 a = __ldg(r0 + k4);
        acc0 += wv.x * a.x + wv.y * a.y + wv.z * a.z + wv.w * a.w;
        a = __ldg(r1 + k4);
        acc1 += wv.x * a.x + wv.y * a.y + wv.z * a.z + wv.w * a.w;
        a = __ldg(r2 + k4);
        acc2 += wv.x * a.x + wv.y * a.y + wv.z * a.z + wv.w * a.w;
        a = __ldg(r3 + k4);
        acc3 += wv.x * a.x + wv.y * a.y + wv.z * a.z + wv.w * a.w;
    }
    g_hsA[(n + 0) * 32 + c] = acc0;   // unscaled h
    g_hsA[(n + 1) * 32 + c] = acc1;
    g_hsA[(n + 2) * 32 + c] = acc2;
    g_hsA[(n + 3) * 32 + c] = acc3;
}

// ---- scale hsA by rsqrt(deg) once degrees are final (float4 streaming) ------
__global__ void scale_kernel() {
    int i = blockIdx.x * 256 + threadIdx.x;      // over NN*8 float4s
    if (i < NN * 8) {
        float dn = rsqrtf((float)g_cnt[i >> 3] + 1.0f);
        float4 v = ((const float4*)g_hsA)[i];
        v.x *= dn; v.y *= dn; v.z *= dn; v.w *= dn;
        ((float4*)g_hsA)[i] = v;
    }
}

// ===== fused: agg(layer) + tanh + feat write + next-layer GEMM (IF=32) =======
// block = 256 threads = 32 nodes; warp = 4 nodes, 8 lanes/node (float4 chans).
__global__ void fused_kernel(const float* __restrict__ b,
                             const float* __restrict__ w,
                             int layer, int par) {
    __shared__ float s_wT[32 * 36];
    __shared__ float s_in[8][128];     // per-warp: 4 nodes x 32 channels
    const float4* hs4 = (const float4*)(par ? g_hsB : g_hsA);
    float*        hso = par ? g_hsA : g_hsB;
    int tid = threadIdx.x;
    for (int i = tid; i < 32 * 32; i += 256) {   // stage W transpose
        int k = i >> 5, c = i & 31;
        s_wT[c * 36 + k] = w[i];
    }
    __syncthreads();

    int warp = tid >> 5, lane = tid & 31;
    int group = lane >> 3, sub = lane & 7;
    int n = blockIdx.x * 32 + warp * 4 + group;

    float4 acc = hs4[n * 8 + sub];               // self-loop term
    int deg = g_cnt[n];
    int base = n * SLOT;
    int maxdeg = __reduce_max_sync(0xffffffffu, deg);
    for (int j = 0; j < maxdeg; j += 8) {
        int idx = (j + sub < deg) ? g_slots[base + j + sub] : 0;
#pragma unroll
        for (int k = 0; k < 8; ++k) {
            int s = __shfl_sync(0xffffffffu, idx, (group << 3) + k);
            if (j + k < deg) {
                float4 v = hs4[s * 8 + sub];
                acc.x += v.x; acc.y += v.y; acc.z += v.z; acc.w += v.w;
            }
        }
    }
    float dn = rsqrtf((float)deg + 1.0f);
    float4 bb = ((const float4*)b)[sub];
    float4 o;
    o.x = tanhf(dn * acc.x + bb.x);
    o.y = tanhf(dn * acc.y + bb.y);
    o.z = tanhf(dn * acc.z + bb.z);
    o.w = tanhf(dn * acc.w + bb.w);
    ((float4*)g_feat)[n * 32 + layer * 8 + sub] = o;
    ((float4*)&s_in[warp][0])[group * 8 + sub] = o;
    __syncwarp();

    // warp-local GEMM: hs_next = (tanh_out @ Wnext) * rsqrt(deg)
    int c = lane;
    float a0 = 0.f, a1 = 0.f, a2 = 0.f, a3 = 0.f;
    const float4* wv4 = (const float4*)&s_wT[c * 36];
    const float4* x0 = (const float4*)&s_in[warp][0];
    const float4* x1 = (const float4*)&s_in[warp][32];
    const float4* x2 = (const float4*)&s_in[warp][64];
    const float4* x3 = (const float4*)&s_in[warp][96];
#pragma unroll
    for (int k4 = 0; k4 < 8; ++k4) {
        float4 wv = wv4[k4];
        float4 a = x0[k4];
        a0 += wv.x * a.x + wv.y * a.y + wv.z * a.z + wv.w * a.w;
        a = x1[k4];
        a1 += wv.x * a.x + wv.y * a.y + wv.z * a.z + wv.w * a.w;
        a = x2[k4];
        a2 += wv.x * a.x + wv.y * a.y + wv.z * a.z + wv.w * a.w;
        a = x3[k4];
        a3 += wv.x * a.x + wv.y * a.y + wv.z * a.z + wv.w * a.w;
    }
    int nn = blockIdx.x * 32 + warp * 4;
    float e0 = rsqrtf((float)g_cnt[nn + 0] + 1.0f);
    float e1 = rsqrtf((float)g_cnt[nn + 1] + 1.0f);
    float e2 = rsqrtf((float)g_cnt[nn + 2] + 1.0f);
    float e3 = rsqrtf((float)g_cnt[nn + 3] + 1.0f);
    hso[(nn + 0) * 32 + c] = a0 * e0;
    hso[(nn + 1) * 32 + c] = a1 * e1;
    hso[(nn + 2) * 32 + c] = a2 * e2;
    hso[(nn + 3) * 32 + c] = a3 * e3;
}

// ---------------- final layer aggregation (layer 3): feat only ---------------
__global__ void agg_final_kernel(const float* __restrict__ b, int par) {
    const float4* hs4 = (const float4*)(par ? g_hsB : g_hsA);
    int t = blockIdx.x * 256 + threadIdx.x;
    int warp = t >> 5;
    int lane = threadIdx.x & 31;
    int group = lane >> 3, sub = lane & 7;
    int n = warp * 4 + group;
    if (n >= NN) return;
    float4 acc = hs4[n * 8 + sub];
    int deg = g_cnt[n];
    int base = n * SLOT;
    int maxdeg = __reduce_max_sync(0xffffffffu, deg);
    for (int j = 0; j < maxdeg; j += 8) {
        int idx = (j + sub < deg) ? g_slots[base + j + sub] : 0;
#pragma unroll
        for (int k = 0; k < 8; ++k) {
            int s = __shfl_sync(0xffffffffu, idx, (group << 3) + k);
            if (j + k < deg) {
                float4 v = hs4[s * 8 + sub];
                acc.x += v.x; acc.y += v.y; acc.z += v.z; acc.w += v.w;
            }
        }
    }
    float dn = rsqrtf((float)deg + 1.0f);
    float4 bb = ((const float4*)b)[sub];
    float4 o;
    o.x = tanhf(dn * acc.x + bb.x);
    o.y = tanhf(dn * acc.y + bb.y);
    o.z = tanhf(dn * acc.z + bb.z);
    o.w = tanhf(dn * acc.w + bb.w);
    ((float4*)g_feat)[n * 32 + 3 * 8 + sub] = o;
}

// ========== head part 1 (per graph): sort-pool + conv1 + pool + conv2 =======
__global__ void head1_kernel(const float* __restrict__ c1w, const float* __restrict__ c1b,
                             const float* __restrict__ c2w, const float* __restrict__ c2b) {
    __shared__ float s_last[NPG];
    __shared__ int   s_ord[KTOP];
    __shared__ float s_topT[128 * 36];  // transposed: [c][k], stride 36
    __shared__ float s_y[16 * KTOP];
    __shared__ float s_p[16 * 17];

    int g = blockIdx.x;
    int tid = threadIdx.x;
    int base = g * NPG;

    if (tid < NPG) s_last[tid] = g_feat[(base + tid) * 128 + 127];
    __syncthreads();

    // stable rank (descending; ties -> lower index first) == argsort(-x)
    if (tid < NPG) {
        float v = s_last[tid];
        int rank = 0;
#pragma unroll 4
        for (int j = 0; j < NPG; ++j) {
            float vj = s_last[j];
            rank += (vj > v) || (vj == v && j < tid);
        }
        if (rank < KTOP) s_ord[rank] = tid;
    }
    __syncthreads();

    for (int t = tid; t < KTOP * 128; t += 128) {
        int k = t >> 7, c = t & 127;
        s_topT[c * 36 + k] = g_feat[(base + s_ord[k]) * 128 + c];
    }
    __syncthreads();

    // conv1 (1x1) + relu : warp spans k -> conflict-free LDS
    for (int t = tid; t < 16 * KTOP; t += 128) {
        int o = t / KTOP, k = t - o * KTOP;
        float acc = c1b[o];
        const float* wr = &c1w[o * 128];
#pragma unroll 8
        for (int c = 0; c < 128; ++c) acc += wr[c] * s_topT[c * 36 + k];
        s_y[o * KTOP + k] = fmaxf(acc, 0.0f);
    }
    __syncthreads();

    for (int t = tid; t < 16 * 17; t += 128) {
        int o = t / 17, l = t - o * 17;
        s_p[t] = fmaxf(s_y[o * KTOP + 2 * l], s_y[o * KTOP + 2 * l + 1]);
    }
    __syncthreads();

    for (int t = tid; t < 32 * 13; t += 128) {
        int oc = t / 13, tt = t - oc * 13;
        float acc = c2b[oc];
        const float* wr = &c2w[oc * 80];
#pragma unroll
        for (int ic = 0; ic < 16; ++ic) {
            const float* pr = &s_p[ic * 17 + tt];
#pragma unroll
            for (int j = 0; j < 5; ++j) acc += wr[ic * 5 + j] * pr[j];
        }
        g_z[g * 416 + t] = fmaxf(acc, 0.0f);
    }
}

// ========== head part 2: fc1 (batched GEMM) + relu + fc2 + sigmoid ==========
__global__ void head2_kernel(const float* __restrict__ f1w, const float* __restrict__ f1b,
                             const float* __restrict__ f2w, const float* __restrict__ f2b,
                             float* __restrict__ out) {
    __shared__ float s_z[8 * 416];
    __shared__ float s_f[8 * 128];
    int tid = threadIdx.x;
    int g0 = blockIdx.x * 8;

    for (int i = tid; i < 8 * 416; i += 256)
        s_z[i] = g_z[g0 * 416 + i];
    __syncthreads();

    int warp = tid >> 5, lane = tid & 31;
    const float4* w4 = (const float4*)f1w;
    const float4* z4 = (const float4*)s_z;

    for (int o = warp; o < 128; o += 8) {
        float p0 = 0.f, p1 = 0.f, p2 = 0.f, p3 = 0.f;
        float p4 = 0.f, p5 = 0.f, p6 = 0.f, p7 = 0.f;
        for (int seg = lane; seg < 104; seg += 32) {
            float4 wv = __ldg(w4 + o * 104 + seg);
            float4 a;
            a = z4[0 * 104 + seg]; p0 += wv.x * a.x + wv.y * a.y + wv.z * a.z + wv.w * a.w;
            a = z4[1 * 104 + seg]; p1 += wv.x * a.x + wv.y * a.y + wv.z * a.z + wv.w * a.w;
            a = z4[2 * 104 + seg]; p2 += wv.x * a.x + wv.y * a.y + wv.z * a.z + wv.w * a.w;
            a = z4[3 * 104 + seg]; p3 += wv.x * a.x + wv.y * a.y + wv.z * a.z + wv.w * a.w;
            a = z4[4 * 104 + seg]; p4 += wv.x * a.x + wv.y * a.y + wv.z * a.z + wv.w * a.w;
            a = z4[5 * 104 + seg]; p5 += wv.x * a.x + wv.y * a.y + wv.z * a.z + wv.w * a.w;
            a = z4[6 * 104 + seg]; p6 += wv.x * a.x + wv.y * a.y + wv.z * a.z + wv.w * a.w;
            a = z4[7 * 104 + seg]; p7 += wv.x * a.x + wv.y * a.y + wv.z * a.z + wv.w * a.w;
        }
#pragma unroll
        for (int m = 16; m > 0; m >>= 1) {
            p0 += __shfl_xor_sync(0xffffffffu, p0, m);
            p1 += __shfl_xor_sync(0xffffffffu, p1, m);
            p2 += __shfl_xor_sync(0xffffffffu, p2, m);
            p3 += __shfl_xor_sync(0xffffffffu, p3, m);
            p4 += __shfl_xor_sync(0xffffffffu, p4, m);
            p5 += __shfl_xor_sync(0xffffffffu, p5, m);
            p6 += __shfl_xor_sync(0xffffffffu, p6, m);
            p7 += __shfl_xor_sync(0xffffffffu, p7, m);
        }
        if (lane == 0) {
            float bb = f1b[o];
            s_f[0 * 128 + o] = fmaxf(p0 + bb, 0.0f);
            s_f[1 * 128 + o] = fmaxf(p1 + bb, 0.0f);
            s_f[2 * 128 + o] = fmaxf(p2 + bb, 0.0f);
            s_f[3 * 128 + o] = fmaxf(p3 + bb, 0.0f);
            s_f[4 * 128 + o] = fmaxf(p4 + bb, 0.0f);
            s_f[5 * 128 + o] = fmaxf(p5 + bb, 0.0f);
            s_f[6 * 128 + o] = fmaxf(p6 + bb, 0.0f);
            s_f[7 * 128 + o] = fmaxf(p7 + bb, 0.0f);
        }
    }
    __syncthreads();

    float acc = f2w[lane]      * s_f[warp * 128 + lane]
              + f2w[lane + 32] * s_f[warp * 128 + lane + 32]
              + f2w[lane + 64] * s_f[warp * 128 + lane + 64]
              + f2w[lane + 96] * s_f[warp * 128 + lane + 96];
#pragma unroll
    for (int m = 16; m > 0; m >>= 1)
        acc += __shfl_xor_sync(0xffffffffu, acc, m);
    if (lane == 0) {
        float z = acc + f2b[0];
        out[g0 + warp] = 1.0f / (1.0f + expf(-z));
    }
}

// ---------------- launch -----------------------------------------------------
extern "C" void kernel_launch(void* const* d_in, const int* in_sizes, int n_in,
                              void* d_out, int out_size) {
    const float* x  = (const float*)d_in[0];
    const int*   ei = (const int*)d_in[1];   // int32 (JAX x64 disabled)
    const float* w[4] = {(const float*)d_in[3], (const float*)d_in[5],
                         (const float*)d_in[7], (const float*)d_in[9]};
    const float* b[4] = {(const float*)d_in[4], (const float*)d_in[6],
                         (const float*)d_in[8], (const float*)d_in[10]};
    const float* c1w = (const float*)d_in[11];
    const float* c1b = (const float*)d_in[12];
    const float* c2w = (const float*)d_in[13];
    const float* c2b = (const float*)d_in[14];
    const float* f1w = (const float*)d_in[15];
    const float* f1b = (const float*)d_in[16];
    const float* f2w = (const float*)d_in[17];
    const float* f2b = (const float*)d_in[18];
    float* out = (float*)d_out;

    // resolve g_cnt's device address once (query, not an allocation)
    static void* cnt_ptr = nullptr;
    if (!cnt_ptr) cudaGetSymbolAddress(&cnt_ptr, g_cnt);

    // fill + layer-0 GEMM overlapped in one grid; scale once degrees final
    build_kernel<<<EB + NB, 256>>>(ei, x, w[0]);        // adjacency + h -> hsA
    scale_kernel<<<(NN * 8 + 255) / 256, 256>>>();      // hsA *= rsqrt(deg)

    fused_kernel<<<NB, 256>>>(b[0], w[1], 0, 0);        // read A -> write B
    fused_kernel<<<NB, 256>>>(b[1], w[2], 1, 1);        // read B -> write A
    fused_kernel<<<NB, 256>>>(b[2], w[3], 2, 0);        // read A -> write B
    agg_final_kernel<<<NB, 256>>>(b[3], 1);             // read B, feat only

    head1_kernel<<<NG, 128>>>(c1w, c1b, c2w, c2b);
    head2_kernel<<<NG / 8, 256>>>(f1w, f1b, f2w, f2b, out);

    // reset degree counters for the next replay (captured memset node)
    cudaMemsetAsync(cnt_ptr, 0, NN * sizeof(int));
}

// round 17
// speedup vs baseline: 1.0334x; 1.0296x over previous
#include <cuda_runtime.h>
#include <math.h>

#define NN 100000
#define NE 3200000
#define HID 32
#define NG 1000
#define NPG 100
#define KTOP 35
#define SLOT 80   // max supported in-degree (Poisson(32); +8.5 sigma)
#define EB ((NE + 255) / 256)   // 12500 fill blocks
#define NB (NN / 32)            // 3125 gemm/agg blocks

// ---------------- scratch (static device globals; no allocation) ------------
__device__ int   g_cnt[NN];                       // in-degree (excl self)
__device__ int   g_slots[NN * SLOT];              // padded adjacency (src ids)
__device__ __align__(16) float g_hsA[NN * HID];   // ping
__device__ __align__(16) float g_hsB[NN * HID];   // pong
__device__ __align__(16) float g_feat[NN * 128];
__device__ __align__(16) float g_z[NG * 416];     // head conv output

// ===== merged: adjacency build (blocks [0,EB)) + layer-0 GEMM (rest) =========
// fill is atomic/latency-bound, gemm is issue-bound -> co-resident blocks
// overlap; gemm writes UNSCALED h (scaling needs g_cnt, done after).
__global__ void build_kernel(const int* __restrict__ ei,
                             const float* __restrict__ x,
                             const float* __restrict__ w) {
    if (blockIdx.x < EB) {
        int e = blockIdx.x * 256 + threadIdx.x;
        if (e < NE) {
            int d = ei[NE + e];
            int pos = atomicAdd(&g_cnt[d], 1);
            if (pos < SLOT) g_slots[d * SLOT + pos] = ei[e];
        }
        return;
    }
    __shared__ float s_wT[32 * 132];
    int tid = threadIdx.x;
    for (int i = tid; i < 128 * 32; i += 256) {
        int k = i >> 5, c = i & 31;
        s_wT[c * 132 + k] = w[i];
    }
    __syncthreads();
    int wi = tid >> 5, c = tid & 31;
    int n = (blockIdx.x - EB) * 32 + wi * 4;
    float acc0 = 0.f, acc1 = 0.f, acc2 = 0.f, acc3 = 0.f;
    const float4* wv4 = (const float4*)&s_wT[c * 132];
    const float4* r0 = (const float4*)&x[(n + 0) * 128];
    const float4* r1 = (const float4*)&x[(n + 1) * 128];
    const float4* r2 = (const float4*)&x[(n + 2) * 128];
    const float4* r3 = (const float4*)&x[(n + 3) * 128];
#pragma unroll 8
    for (int k4 = 0; k4 < 32; ++k4) {
        float4 wv = wv4[k4];
        float4 a = __ldg(r0 + k4);
        acc0 += wv.x * a.x + wv.y * a.y + wv.z * a.z + wv.w * a.w;
        a = __ldg(r1 + k4);
        acc1 += wv.x * a.x + wv.y * a.y + wv.z * a.z + wv.w * a.w;
        a = __ldg(r2 + k4);
        acc2 += wv.x * a.x + wv.y * a.y + wv.z * a.z + wv.w * a.w;
        a = __ldg(r3 + k4);
        acc3 += wv.x * a.x + wv.y * a.y + wv.z * a.z + wv.w * a.w;
    }
    g_hsA[(n + 0) * 32 + c] = acc0;   // unscaled h
    g_hsA[(n + 1) * 32 + c] = acc1;
    g_hsA[(n + 2) * 32 + c] = acc2;
    g_hsA[(n + 3) * 32 + c] = acc3;
}

// ---- scale hsA by rsqrt(deg) once degrees are final (float4 streaming) ------
__global__ void scale_kernel() {
    int i = blockIdx.x * 256 + threadIdx.x;      // over NN*8 float4s
    if (i < NN * 8) {
        float dn = rsqrtf((float)g_cnt[i >> 3] + 1.0f);
        float4 v = ((const float4*)g_hsA)[i];
        v.x *= dn; v.y *= dn; v.z *= dn; v.w *= dn;
        ((float4*)g_hsA)[i] = v;
    }
}

// ===== fused: agg(layer) + tanh + feat write + next-layer GEMM (IF=32) =======
// block = 256 threads = 32 nodes; warp = 4 nodes, 8 lanes/node (float4 chans).
__global__ void fused_kernel(const float* __restrict__ b,
                             const float* __restrict__ w,
                             int layer, int par) {
    __shared__ float s_wT[32 * 36];
    __shared__ float s_in[8][128];     // per-warp: 4 nodes x 32 channels
    const float4* hs4 = (const float4*)(par ? g_hsB : g_hsA);
    float*        hso = par ? g_hsA : g_hsB;
    int tid = threadIdx.x;
    for (int i = tid; i < 32 * 32; i += 256) {   // stage W transpose
        int k = i >> 5, c = i & 31;
        s_wT[c * 36 + k] = w[i];
    }
    __syncthreads();

    int warp = tid >> 5, lane = tid & 31;
    int group = lane >> 3, sub = lane & 7;
    int n = blockIdx.x * 32 + warp * 4 + group;

    float4 acc = hs4[n * 8 + sub];               // self-loop term
    int deg = g_cnt[n];
    int base = n * SLOT;
    int maxdeg = __reduce_max_sync(0xffffffffu, deg);
    for (int j = 0; j < maxdeg; j += 8) {
        int idx = (j + sub < deg) ? g_slots[base + j + sub] : 0;
#pragma unroll
        for (int k = 0; k < 8; ++k) {
            int s = __shfl_sync(0xffffffffu, idx, (group << 3) + k);
            if (j + k < deg) {
                float4 v = hs4[s * 8 + sub];
                acc.x += v.x; acc.y += v.y; acc.z += v.z; acc.w += v.w;
            }
        }
    }
    float dn = rsqrtf((float)deg + 1.0f);
    float4 bb = ((const float4*)b)[sub];
    float4 o;
    o.x = tanhf(dn * acc.x + bb.x);
    o.y = tanhf(dn * acc.y + bb.y);
    o.z = tanhf(dn * acc.z + bb.z);
    o.w = tanhf(dn * acc.w + bb.w);
    ((float4*)g_feat)[n * 32 + layer * 8 + sub] = o;
    ((float4*)&s_in[warp][0])[group * 8 + sub] = o;
    __syncwarp();

    // warp-local GEMM: hs_next = (tanh_out @ Wnext) * rsqrt(deg)
    int c = lane;
    float a0 = 0.f, a1 = 0.f, a2 = 0.f, a3 = 0.f;
    const float4* wv4 = (const float4*)&s_wT[c * 36];
    const float4* x0 = (const float4*)&s_in[warp][0];
    const float4* x1 = (const float4*)&s_in[warp][32];
    const float4* x2 = (const float4*)&s_in[warp][64];
    const float4* x3 = (const float4*)&s_in[warp][96];
#pragma unroll
    for (int k4 = 0; k4 < 8; ++k4) {
        float4 wv = wv4[k4];
        float4 a = x0[k4];
        a0 += wv.x * a.x + wv.y * a.y + wv.z * a.z + wv.w * a.w;
        a = x1[k4];
        a1 += wv.x * a.x + wv.y * a.y + wv.z * a.z + wv.w * a.w;
        a = x2[k4];
        a2 += wv.x * a.x + wv.y * a.y + wv.z * a.z + wv.w * a.w;
        a = x3[k4];
        a3 += wv.x * a.x + wv.y * a.y + wv.z * a.z + wv.w * a.w;
    }
    int nn = blockIdx.x * 32 + warp * 4;
    float e0 = rsqrtf((float)g_cnt[nn + 0] + 1.0f);
    float e1 = rsqrtf((float)g_cnt[nn + 1] + 1.0f);
    float e2 = rsqrtf((float)g_cnt[nn + 2] + 1.0f);
    float e3 = rsqrtf((float)g_cnt[nn + 3] + 1.0f);
    hso[(nn + 0) * 32 + c] = a0 * e0;
    hso[(nn + 1) * 32 + c] = a1 * e1;
    hso[(nn + 2) * 32 + c] = a2 * e2;
    hso[(nn + 3) * 32 + c] = a3 * e3;
}

// ---------------- final layer aggregation (layer 3): feat only ---------------
__global__ void agg_final_kernel(const float* __restrict__ b, int par) {
    const float4* hs4 = (const float4*)(par ? g_hsB : g_hsA);
    int t = blockIdx.x * 256 + threadIdx.x;
    int warp = t >> 5;
    int lane = threadIdx.x & 31;
    int group = lane >> 3, sub = lane & 7;
    int n = warp * 4 + group;
    if (n >= NN) return;
    float4 acc = hs4[n * 8 + sub];
    int deg = g_cnt[n];
    int base = n * SLOT;
    int maxdeg = __reduce_max_sync(0xffffffffu, deg);
    for (int j = 0; j < maxdeg; j += 8) {
        int idx = (j + sub < deg) ? g_slots[base + j + sub] : 0;
#pragma unroll
        for (int k = 0; k < 8; ++k) {
            int s = __shfl_sync(0xffffffffu, idx, (group << 3) + k);
            if (j + k < deg) {
                float4 v = hs4[s * 8 + sub];
                acc.x += v.x; acc.y += v.y; acc.z += v.z; acc.w += v.w;
            }
        }
    }
    float dn = rsqrtf((float)deg + 1.0f);
    float4 bb = ((const float4*)b)[sub];
    float4 o;
    o.x = tanhf(dn * acc.x + bb.x);
    o.y = tanhf(dn * acc.y + bb.y);
    o.z = tanhf(dn * acc.z + bb.z);
    o.w = tanhf(dn * acc.w + bb.w);
    ((float4*)g_feat)[n * 32 + 3 * 8 + sub] = o;
}

// ---------------- cleanup (separate kernel — R14-proven config) --------------
__global__ void cleanup_kernel() {
    int i = blockIdx.x * 256 + threadIdx.x;
    if (i < NN) g_cnt[i] = 0;
}

// ========== head part 1 (per graph): sort-pool + conv1 + pool + conv2 =======
// 256 threads: halves each phase's critical path vs 128 (work loops are
// stride-blockDim; per-output accumulation order unchanged).
__global__ void head1_kernel(const float* __restrict__ c1w, const float* __restrict__ c1b,
                             const float* __restrict__ c2w, const float* __restrict__ c2b) {
    __shared__ float s_last[NPG];
    __shared__ int   s_ord[KTOP];
    __shared__ float s_topT[128 * 36];  // transposed: [c][k], stride 36
    __shared__ float s_y[16 * KTOP];
    __shared__ float s_p[16 * 17];

    int g = blockIdx.x;
    int tid = threadIdx.x;
    int base = g * NPG;

    if (tid < NPG) s_last[tid] = g_feat[(base + tid) * 128 + 127];
    __syncthreads();

    // stable rank (descending; ties -> lower index first) == argsort(-x)
    if (tid < NPG) {
        float v = s_last[tid];
        int rank = 0;
#pragma unroll 4
        for (int j = 0; j < NPG; ++j) {
            float vj = s_last[j];
            rank += (vj > v) || (vj == v && j < tid);
        }
        if (rank < KTOP) s_ord[rank] = tid;
    }
    __syncthreads();

    for (int t = tid; t < KTOP * 128; t += 256) {
        int k = t >> 7, c = t & 127;
        s_topT[c * 36 + k] = g_feat[(base + s_ord[k]) * 128 + c];
    }
    __syncthreads();

    // conv1 (1x1) + relu : threads span k fastest -> conflict-free LDS
    for (int t = tid; t < 16 * KTOP; t += 256) {
        int o = t / KTOP, k = t - o * KTOP;
        float acc = c1b[o];
        const float* wr = &c1w[o * 128];
#pragma unroll 8
        for (int c = 0; c < 128; ++c) acc += wr[c] * s_topT[c * 36 + k];
        s_y[o * KTOP + k] = fmaxf(acc, 0.0f);
    }
    __syncthreads();

    for (int t = tid; t < 16 * 17; t += 256) {
        int o = t / 17, l = t - o * 17;
        s_p[t] = fmaxf(s_y[o * KTOP + 2 * l], s_y[o * KTOP + 2 * l + 1]);
    }
    __syncthreads();

    for (int t = tid; t < 32 * 13; t += 256) {
        int oc = t / 13, tt = t - oc * 13;
        float acc = c2b[oc];
        const float* wr = &c2w[oc * 80];
#pragma unroll
        for (int ic = 0; ic < 16; ++ic) {
            const float* pr = &s_p[ic * 17 + tt];
#pragma unroll
            for (int j = 0; j < 5; ++j) acc += wr[ic * 5 + j] * pr[j];
        }
        g_z[g * 416 + t] = fmaxf(acc, 0.0f);
    }
}

// ========== head part 2: fc1 (batched GEMM) + relu + fc2 + sigmoid ==========
__global__ void head2_kernel(const float* __restrict__ f1w, const float* __restrict__ f1b,
                             const float* __restrict__ f2w, const float* __restrict__ f2b,
                             float* __restrict__ out) {
    __shared__ float s_z[8 * 416];
    __shared__ float s_f[8 * 128];
    int tid = threadIdx.x;
    int g0 = blockIdx.x * 8;

    for (int i = tid; i < 8 * 416; i += 256)
        s_z[i] = g_z[g0 * 416 + i];
    __syncthreads();

    int warp = tid >> 5, lane = tid & 31;
    const float4* w4 = (const float4*)f1w;
    const float4* z4 = (const float4*)s_z;

    for (int o = warp; o < 128; o += 8) {
        float p0 = 0.f, p1 = 0.f, p2 = 0.f, p3 = 0.f;
        float p4 = 0.f, p5 = 0.f, p6 = 0.f, p7 = 0.f;
        for (int seg = lane; seg < 104; seg += 32) {
            float4 wv = __ldg(w4 + o * 104 + seg);
            float4 a;
            a = z4[0 * 104 + seg]; p0 += wv.x * a.x + wv.y * a.y + wv.z * a.z + wv.w * a.w;
            a = z4[1 * 104 + seg]; p1 += wv.x * a.x + wv.y * a.y + wv.z * a.z + wv.w * a.w;
            a = z4[2 * 104 + seg]; p2 += wv.x * a.x + wv.y * a.y + wv.z * a.z + wv.w * a.w;
            a = z4[3 * 104 + seg]; p3 += wv.x * a.x + wv.y * a.y + wv.z * a.z + wv.w * a.w;
            a = z4[4 * 104 + seg]; p4 += wv.x * a.x + wv.y * a.y + wv.z * a.z + wv.w * a.w;
            a = z4[5 * 104 + seg]; p5 += wv.x * a.x + wv.y * a.y + wv.z * a.z + wv.w * a.w;
            a = z4[6 * 104 + seg]; p6 += wv.x * a.x + wv.y * a.y + wv.z * a.z + wv.w * a.w;
            a = z4[7 * 104 + seg]; p7 += wv.x * a.x + wv.y * a.y + wv.z * a.z + wv.w * a.w;
        }
#pragma unroll
        for (int m = 16; m > 0; m >>= 1) {
            p0 += __shfl_xor_sync(0xffffffffu, p0, m);
            p1 += __shfl_xor_sync(0xffffffffu, p1, m);
            p2 += __shfl_xor_sync(0xffffffffu, p2, m);
            p3 += __shfl_xor_sync(0xffffffffu, p3, m);
            p4 += __shfl_xor_sync(0xffffffffu, p4, m);
            p5 += __shfl_xor_sync(0xffffffffu, p5, m);
            p6 += __shfl_xor_sync(0xffffffffu, p6, m);
            p7 += __shfl_xor_sync(0xffffffffu, p7, m);
        }
        if (lane == 0) {
            float bb = f1b[o];
            s_f[0 * 128 + o] = fmaxf(p0 + bb, 0.0f);
            s_f[1 * 128 + o] = fmaxf(p1 + bb, 0.0f);
            s_f[2 * 128 + o] = fmaxf(p2 + bb, 0.0f);
            s_f[3 * 128 + o] = fmaxf(p3 + bb, 0.0f);
            s_f[4 * 128 + o] = fmaxf(p4 + bb, 0.0f);
            s_f[5 * 128 + o] = fmaxf(p5 + bb, 0.0f);
            s_f[6 * 128 + o] = fmaxf(p6 + bb, 0.0f);
            s_f[7 * 128 + o] = fmaxf(p7 + bb, 0.0f);
        }
    }
    __syncthreads();

    float acc = f2w[lane]      * s_f[warp * 128 + lane]
              + f2w[lane + 32] * s_f[warp * 128 + lane + 32]
              + f2w[lane + 64] * s_f[warp * 128 + lane + 64]
              + f2w[lane + 96] * s_f[warp * 128 + lane + 96];
#pragma unroll
    for (int m = 16; m > 0; m >>= 1)
        acc += __shfl_xor_sync(0xffffffffu, acc, m);
    if (lane == 0) {
        float z = acc + f2b[0];
        out[g0 + warp] = 1.0f / (1.0f + expf(-z));
    }
}

// ---------------- launch -----------------------------------------------------
extern "C" void kernel_launch(void* const* d_in, const int* in_sizes, int n_in,
                              void* d_out, int out_size) {
    const float* x  = (const float*)d_in[0];
    const int*   ei = (const int*)d_in[1];   // int32 (JAX x64 disabled)
    const float* w[4] = {(const float*)d_in[3], (const float*)d_in[5],
                         (const float*)d_in[7], (const float*)d_in[9]};
    const float* b[4] = {(const float*)d_in[4], (const float*)d_in[6],
                         (const float*)d_in[8], (const float*)d_in[10]};
    const float* c1w = (const float*)d_in[11];
    const float* c1b = (const float*)d_in[12];
    const float* c2w = (const float*)d_in[13];
    const float* c2b = (const float*)d_in[14];
    const float* f1w = (const float*)d_in[15];
    const float* f1b = (const float*)d_in[16];
    const float* f2w = (const float*)d_in[17];
    const float* f2b = (const float*)d_in[18];
    float* out = (float*)d_out;

    // fill + layer-0 GEMM overlapped in one grid; scale once degrees final
    build_kernel<<<EB + NB, 256>>>(ei, x, w[0]);        // adjacency + h -> hsA
    scale_kernel<<<(NN * 8 + 255) / 256, 256>>>();      // hsA *= rsqrt(deg)

    fused_kernel<<<NB, 256>>>(b[0], w[1], 0, 0);        // read A -> write B
    fused_kernel<<<NB, 256>>>(b[1], w[2], 1, 1);        // read B -> write A
    fused_kernel<<<NB, 256>>>(b[2], w[3], 2, 0);        // read A -> write B
    agg_final_kernel<<<NB, 256>>>(b[3], 1);             // read B, feat only

    head1_kernel<<<NG, 256>>>(c1w, c1b, c2w, c2b);
    head2_kernel<<<NG / 8, 256>>>(f1w, f1b, f2w, f2b, out);

    cleanup_kernel<<<(NN + 255) / 256, 256>>>();
}